// round 3
// baseline (speedup 1.0000x reference)
#include <cuda_runtime.h>

#define NN   16
#define RAD2 0.25f
#define EPSV 1e-4f
#define NPTS 8192
#define NB   4
#define TILE 2048
#define TPB  128

__global__ void zero_out_kernel(float* out) {
    if (threadIdx.x == 0) out[0] = 0.f;
}

__global__ __launch_bounds__(TPB) void repulsion_kernel(const float* __restrict__ pts,
                                                        float* __restrict__ out) {
    __shared__ float4 tile[TILE];
    __shared__ float  red[TPB / 32];

    const int b  = blockIdx.y;
    const int qi = blockIdx.x * TPB + threadIdx.x;   // query index within batch
    const float* base = pts + (size_t)b * NPTS * 3;

    const float qx = base[qi * 3 + 0];
    const float qy = base[qi * 3 + 1];
    const float qz = base[qi * 3 + 2];

    // 16 smallest within-radius squared distances; sentinel = RAD2.
    float arr[NN];
    #pragma unroll
    for (int k = 0; k < NN; k++) arr[k] = RAD2;
    float curmax = RAD2;
    int   maxidx = 0;

    for (int t0 = 0; t0 < NPTS; t0 += TILE) {
        __syncthreads();
        // Cooperative tile load, float4-padded for single LDS.128 in hot loop.
        #pragma unroll
        for (int u = 0; u < TILE / TPB; u++) {
            int i = u * TPB + threadIdx.x;
            int j = t0 + i;
            tile[i] = make_float4(base[j * 3 + 0], base[j * 3 + 1], base[j * 3 + 2], 0.f);
        }
        __syncthreads();

        #pragma unroll 8
        for (int t = 0; t < TILE; t++) {
            float4 c = tile[t];
            float dx = qx - c.x;
            float dy = qy - c.y;
            float dz = qz - c.z;
            float d2 = fmaf(dx, dx, fmaf(dy, dy, dz * dz));
            if (d2 < curmax) {              // rare (~0.4% per lane)
                if ((t0 + t) != qi) {       // exclude self
                    // Replace current max slot without dynamic indexing (keep arr in regs).
                    #pragma unroll
                    for (int k = 0; k < NN; k++)
                        if (k == maxidx) arr[k] = d2;
                    // Recompute max + argmax.
                    curmax = arr[0]; maxidx = 0;
                    #pragma unroll
                    for (int k = 1; k < NN; k++) {
                        if (arr[k] > curmax) { curmax = arr[k]; maxidx = k; }
                    }
                }
            }
        }
    }

    // Sentinels (== RAD2) contribute 0, matching the reference's strict d2 < RADIUS2 mask.
    float loss = 0.f;
    #pragma unroll
    for (int k = 0; k < NN; k++)
        if (arr[k] < RAD2) loss += rsqrtf(arr[k] + EPSV);

    loss *= (1.f / ((float)NB * (float)NPTS * (float)NN));   // global mean scale

    // Block reduction: warp shuffle -> shared -> single atomic per block.
    #pragma unroll
    for (int o = 16; o > 0; o >>= 1) loss += __shfl_down_sync(0xffffffffu, loss, o);
    if ((threadIdx.x & 31) == 0) red[threadIdx.x >> 5] = loss;
    __syncthreads();
    if (threadIdx.x < TPB / 32) {
        loss = red[threadIdx.x];
        #pragma unroll
        for (int o = TPB / 64; o > 0; o >>= 1)
            loss += __shfl_down_sync((unsigned)((1u << (TPB / 32)) - 1u), loss, o);
        if (threadIdx.x == 0) atomicAdd(out, loss);
    }
}

extern "C" void kernel_launch(void* const* d_in, const int* in_sizes, int n_in,
                              void* d_out, int out_size) {
    const float* pts = (const float*)d_in[0];
    float* out = (float*)d_out;

    zero_out_kernel<<<1, 32>>>(out);
    dim3 grid(NPTS / TPB, NB);
    repulsion_kernel<<<grid, TPB>>>(pts, out);
}

// round 6
// speedup vs baseline: 1.8250x; 1.8250x over previous
#include <cuda_runtime.h>

#define NN    16
#define RAD2  0.25f
#define EPSV  1e-4f
#define NPTS  8192
#define NB    4
#define HALF  (NPTS / 2)
#define TILE  2048
#define TPB   128
#define MTPB  256

// Per-(half, batch, query) top-16 candidate lists. 2*4*8192*16*4B = 4 MB.
__device__ float g_scratch[2 * NB * NPTS * NN];

__global__ void zero_out_kernel(float* out) {
    if (threadIdx.x == 0) out[0] = 0.f;
}

// Each CTA handles TPB queries over ONE HALF of the candidate range.
__global__ __launch_bounds__(TPB) void repulsion_half_kernel(const float* __restrict__ pts) {
    __shared__ float4 tile[TILE];

    const int b    = blockIdx.z;
    const int half = blockIdx.y;
    const int qi   = blockIdx.x * TPB + threadIdx.x;
    const float* base = pts + (size_t)b * NPTS * 3;

    const float qx = base[qi * 3 + 0];
    const float qy = base[qi * 3 + 1];
    const float qz = base[qi * 3 + 2];

    // 16 smallest within-radius d2 from this half; sentinel = RAD2.
    float arr[NN];
    #pragma unroll
    for (int k = 0; k < NN; k++) arr[k] = RAD2;
    float curmax = RAD2;
    int   maxidx = 0;

    const int cbeg = half * HALF;
    for (int t0 = cbeg; t0 < cbeg + HALF; t0 += TILE) {
        __syncthreads();
        #pragma unroll
        for (int u = 0; u < TILE / TPB; u++) {
            int i = u * TPB + threadIdx.x;
            int j = t0 + i;
            tile[i] = make_float4(base[j * 3 + 0], base[j * 3 + 1], base[j * 3 + 2], 0.f);
        }
        __syncthreads();

        #pragma unroll 8
        for (int t = 0; t < TILE; t++) {
            float4 c = tile[t];
            float dx = qx - c.x;
            float dy = qy - c.y;
            float dz = qz - c.z;
            float d2 = fmaf(dx, dx, fmaf(dy, dy, dz * dz));
            bool want = (d2 < curmax) && ((t0 + t) != qi);
            // Warp-uniform guard -> real branch, not if-conversion: the ~50-instr
            // insert body issues only when some lane actually inserts (~24% of iters).
            if (__ballot_sync(0xffffffffu, want)) {
                if (want) {
                    #pragma unroll
                    for (int k = 0; k < NN; k++)
                        if (k == maxidx) arr[k] = d2;       // static-indexed replace
                    curmax = arr[0]; maxidx = 0;            // recompute max/argmax
                    #pragma unroll
                    for (int k = 1; k < NN; k++) {
                        if (arr[k] > curmax) { curmax = arr[k]; maxidx = k; }
                    }
                }
            }
        }
    }

    // Write this half's list (64B contiguous per query -> float4-friendly for merge).
    float* dst = g_scratch + (size_t)(((half * NB + b) * NPTS + qi)) * NN;
    #pragma unroll
    for (int k = 0; k < NN; k += 4)
        *(float4*)(dst + k) = make_float4(arr[k], arr[k + 1], arr[k + 2], arr[k + 3]);
}

// Merge the two 16-lists per query: exact 16-smallest of 32 (rank-count with
// index tiebreak), sum rsqrt for values strictly inside the radius, reduce.
__global__ __launch_bounds__(MTPB) void merge_kernel(float* __restrict__ out) {
    __shared__ float red[MTPB / 32];

    const int gid = blockIdx.x * MTPB + threadIdx.x;   // 0 .. NB*NPTS-1
    const int b   = gid / NPTS;
    const int qi  = gid - b * NPTS;

    float v[2 * NN];
    #pragma unroll
    for (int h = 0; h < 2; h++) {
        const float* src = g_scratch + (size_t)(((h * NB + b) * NPTS + qi)) * NN;
        #pragma unroll
        for (int k = 0; k < NN; k += 4) {
            float4 p = *(const float4*)(src + k);
            v[h * NN + k + 0] = p.x;
            v[h * NN + k + 1] = p.y;
            v[h * NN + k + 2] = p.z;
            v[h * NN + k + 3] = p.w;
        }
    }

    float loss = 0.f;
    for (int i = 0; i < 2 * NN; i++) {
        int rank = 0;
        #pragma unroll
        for (int j = 0; j < 2 * NN; j++)
            rank += (v[j] < v[i]) || (v[j] == v[i] && j < i);
        if (rank < NN && v[i] < RAD2)
            loss += rsqrtf(v[i] + EPSV);
    }

    loss *= (1.f / ((float)NB * (float)NPTS * (float)NN));

    #pragma unroll
    for (int o = 16; o > 0; o >>= 1) loss += __shfl_down_sync(0xffffffffu, loss, o);
    if ((threadIdx.x & 31) == 0) red[threadIdx.x >> 5] = loss;
    __syncthreads();
    if (threadIdx.x < MTPB / 32) {
        loss = red[threadIdx.x];
        #pragma unroll
        for (int o = MTPB / 64; o > 0; o >>= 1)
            loss += __shfl_down_sync(0xffu, loss, o);
        if (threadIdx.x == 0) atomicAdd(out, loss);
    }
}

extern "C" void kernel_launch(void* const* d_in, const int* in_sizes, int n_in,
                              void* d_out, int out_size) {
    const float* pts = (const float*)d_in[0];
    float* out = (float*)d_out;

    zero_out_kernel<<<1, 32>>>(out);
    dim3 grid(NPTS / TPB, 2, NB);           // 512 CTAs -> ~14 warps/SM
    repulsion_half_kernel<<<grid, TPB>>>(pts);
    merge_kernel<<<(NB * NPTS) / MTPB, MTPB>>>(out);
}

// round 8
// speedup vs baseline: 1.9162x; 1.0499x over previous
#include <cuda_runtime.h>

#define NN    16
#define RAD2  0.25f
#define EPSV  1e-4f
#define NPTS  8192
#define NB    4
#define NSPLIT 4
#define QUART (NPTS / NSPLIT)     // 2048 candidates per split = one tile
#define TPB   128
#define MTPB  256

// Per-(split, batch, query) top-16 lists. 4*4*8192*16*4B = 8 MB.
__device__ float g_scratch[NSPLIT * NB * NPTS * NN];

__global__ void zero_out_kernel(float* out) {
    if (threadIdx.x == 0) out[0] = 0.f;
}

// Each CTA: TPB queries over ONE QUARTER of the candidate range (single tile).
__global__ __launch_bounds__(TPB) void repulsion_quarter_kernel(const float* __restrict__ pts) {
    __shared__ float4 tile[QUART];

    const int b    = blockIdx.z;
    const int quad = blockIdx.y;
    const int qi   = blockIdx.x * TPB + threadIdx.x;
    const float* base = pts + (size_t)b * NPTS * 3;

    const float qx = base[qi * 3 + 0];
    const float qy = base[qi * 3 + 1];
    const float qz = base[qi * 3 + 2];

    // 16 smallest within-radius d2 from this quarter; sentinel = RAD2.
    float arr[NN];
    #pragma unroll
    for (int k = 0; k < NN; k++) arr[k] = RAD2;
    float curmax = RAD2;
    int   maxidx = 0;

    const int cbeg = quad * QUART;
    #pragma unroll
    for (int u = 0; u < QUART / TPB; u++) {
        int i = u * TPB + threadIdx.x;
        int j = cbeg + i;
        tile[i] = make_float4(base[j * 3 + 0], base[j * 3 + 1], base[j * 3 + 2], 0.f);
    }
    __syncthreads();

    #pragma unroll 8
    for (int t = 0; t < QUART; t++) {
        float4 c = tile[t];
        float dx = qx - c.x;
        float dy = qy - c.y;
        float dz = qz - c.z;
        float d2 = fmaf(dx, dx, fmaf(dy, dy, dz * dz));
        bool want = (d2 < curmax) && ((cbeg + t) != qi);
        // Warp-uniform guard -> real branch: ~50-instr insert body issues only
        // when some lane inserts (~25% of warp-iterations).
        if (__ballot_sync(0xffffffffu, want)) {
            if (want) {
                #pragma unroll
                for (int k = 0; k < NN; k++)
                    if (k == maxidx) arr[k] = d2;       // static-indexed replace
                curmax = arr[0]; maxidx = 0;            // recompute max/argmax
                #pragma unroll
                for (int k = 1; k < NN; k++)
                    if (arr[k] > curmax) { curmax = arr[k]; maxidx = k; }
            }
        }
    }

    float* dst = g_scratch + (size_t)(((quad * NB + b) * NPTS + qi)) * NN;
    #pragma unroll
    for (int k = 0; k < NN; k += 4)
        *(float4*)(dst + k) = make_float4(arr[k], arr[k + 1], arr[k + 2], arr[k + 3]);
}

// Merge 4 quarter-lists per query by re-running the register-resident insert
// over the 64 values (exact: strict < handles sentinels/dups/radius), then reduce.
__global__ __launch_bounds__(MTPB) void merge_kernel(float* __restrict__ out) {
    __shared__ float red[MTPB / 32];

    const int gid = blockIdx.x * MTPB + threadIdx.x;   // 0 .. NB*NPTS-1
    const int b   = gid / NPTS;
    const int qi  = gid - b * NPTS;

    float arr[NN];
    #pragma unroll
    for (int k = 0; k < NN; k++) arr[k] = RAD2;
    float curmax = RAD2;
    int   maxidx = 0;

    #pragma unroll
    for (int h = 0; h < NSPLIT; h++) {
        const float* src = g_scratch + (size_t)(((h * NB + b) * NPTS + qi)) * NN;
        #pragma unroll
        for (int k4 = 0; k4 < NN; k4 += 4) {
            float4 p = *(const float4*)(src + k4);
            float vv[4] = {p.x, p.y, p.z, p.w};
            #pragma unroll
            for (int j = 0; j < 4; j++) {
                float d2 = vv[j];
                if (d2 < curmax) {
                    #pragma unroll
                    for (int k = 0; k < NN; k++)
                        if (k == maxidx) arr[k] = d2;
                    curmax = arr[0]; maxidx = 0;
                    #pragma unroll
                    for (int k = 1; k < NN; k++)
                        if (arr[k] > curmax) { curmax = arr[k]; maxidx = k; }
                }
            }
        }
    }

    float loss = 0.f;
    #pragma unroll
    for (int k = 0; k < NN; k++)
        if (arr[k] < RAD2) loss += rsqrtf(arr[k] + EPSV);
    loss *= (1.f / ((float)NB * (float)NPTS * (float)NN));

    #pragma unroll
    for (int o = 16; o > 0; o >>= 1) loss += __shfl_down_sync(0xffffffffu, loss, o);
    if ((threadIdx.x & 31) == 0) red[threadIdx.x >> 5] = loss;
    __syncthreads();
    if (threadIdx.x < MTPB / 32) {
        loss = red[threadIdx.x];
        #pragma unroll
        for (int o = MTPB / 64; o > 0; o >>= 1)
            loss += __shfl_down_sync(0xffu, loss, o);
        if (threadIdx.x == 0) atomicAdd(out, loss);
    }
}

extern "C" void kernel_launch(void* const* d_in, const int* in_sizes, int n_in,
                              void* d_out, int out_size) {
    const float* pts = (const float*)d_in[0];
    float* out = (float*)d_out;

    zero_out_kernel<<<1, 32>>>(out);
    dim3 grid(NPTS / TPB, NSPLIT, NB);      // 1024 CTAs -> ~24 warps/SM
    repulsion_quarter_kernel<<<grid, TPB>>>(pts);
    merge_kernel<<<(NB * NPTS) / MTPB, MTPB>>>(out);
}